// round 3
// baseline (speedup 1.0000x reference)
#include <cuda_runtime.h>
#include <cstdint>

// ---------------- problem constants (fixed shapes) ----------------
#define TLEN   32768
#define BATCH  4
#define RCH    64          // residual channels
#define GCH    128         // 2R gate channels
#define NLAY   9
#define NCOUT  256

// ---------------- device scratch (allowed: __device__ globals) ----------------
__device__ float g_hA  [BATCH * RCH * TLEN];     // 33.5 MB
__device__ float g_hB  [BATCH * RCH * TLEN];     // 33.5 MB
__device__ float g_skip[BATCH * RCH * TLEN];     // 33.5 MB  (sum_l W1_l * z_l accumulator)
__device__ float g_WcT [NLAY * 3 * RCH * GCH];   // [l][k][ci][co]   (co = 128 contiguous)
__device__ float g_WoT [NLAY * RCH * RCH];       // [l][rl][r]
__device__ float g_W1T [NLAY * RCH * RCH];       // [l][rl][r]
__device__ float g_W2T [RCH * NCOUT];            // [r][co]

// ---------------- weight transpose / repack (runs once per launch) ----------------
__global__ void k_prep(const float* __restrict__ wc,   // (L,128,64,3)
                       const float* __restrict__ wo,   // (L,64,64,1)
                       const float* __restrict__ w1,   // (64, 64*L, 1)
                       const float* __restrict__ w2)   // (256,64,1)
{
    const int N_WC = NLAY * 3 * RCH * GCH;   // 221184
    const int N_WO = NLAY * RCH * RCH;       // 36864
    const int N_W1 = NLAY * RCH * RCH;       // 36864
    const int N_W2 = RCH * NCOUT;            // 16384
    const int total = N_WC + N_WO + N_W1 + N_W2;
    for (int u = blockIdx.x * blockDim.x + threadIdx.x; u < total;
         u += gridDim.x * blockDim.x) {
        int v = u;
        if (v < N_WC) {
            int l  = v / 24576;
            int r0 = v % 24576;
            int k  = r0 / 8192;
            int r1 = r0 % 8192;
            int ci = r1 / GCH;
            int co = r1 % GCH;
            g_WcT[v] = wc[((l * GCH + co) * RCH + ci) * 3 + k];
            continue;
        }
        v -= N_WC;
        if (v < N_WO) {
            int l  = v / 4096;
            int r1 = v % 4096;
            int rl = r1 / RCH;
            int r  = r1 % RCH;
            g_WoT[v] = wo[(l * RCH + r) * RCH + rl];
            continue;
        }
        v -= N_WO;
        if (v < N_W1) {
            int l  = v / 4096;
            int r1 = v % 4096;
            int rl = r1 / RCH;
            int r  = r1 % RCH;
            g_W1T[v] = w1[r * (RCH * NLAY) + l * RCH + rl];
            continue;
        }
        v -= N_W1;
        {
            int r  = v / NCOUT;
            int co = v % NCOUT;
            g_W2T[v] = w2[co * RCH + r];
        }
    }
}

// ---------------- input 1x1 conv + tanh, and zero skip accumulator ----------------
__global__ __launch_bounds__(256) void k_init(const float* __restrict__ x,
                                              const float* __restrict__ wi,
                                              const float* __restrict__ bi)
{
    __shared__ float xs[128];
    __shared__ float wis[RCH];
    __shared__ float bis[RCH];
    const int b  = blockIdx.y;
    const int t0 = blockIdx.x * 128;
    const int tid = threadIdx.x;
    if (tid < 128)          xs[tid]        = x[b * TLEN + t0 + tid];
    else if (tid < 192)     wis[tid - 128] = wi[tid - 128];
    else                    bis[tid - 192] = bi[tid - 192];
    __syncthreads();
    for (int u = tid; u < RCH * 128; u += 256) {
        int r = u >> 7, j = u & 127;
        size_t idx = (size_t)(b * RCH + r) * TLEN + t0 + j;
        g_hA[idx]   = tanhf(wis[r] * xs[j] + bis[r]);
        g_skip[idx] = 0.0f;
    }
}

// ---------------- fused dilated-conv + gate + residual + skip-projection ----------------
// One block = one (batch, 128-wide time tile). 256 threads.
// smem layout (floats):
//   [0 .. 8192)      Hs : input tile for current tap, [ci][t] 64x128   (phase1)
//                    Zs : gated activations [rl][t]   64x128           (phase2/3, overlay)
//   [8192 .. 16384)  Ws : weights for current tap, [ci][co] 64x128     (phase1)
//   [16384.. 20480)  WoS: residual 1x1 weights  [rl][r] 64x64
//   [20480.. 24576)  W1S: skip-proj  weights    [rl][r] 64x64
//   [24576.. 24704)  bcS: conv bias (128)
//   [24704.. 24768)  boS: residual bias (64)
#define LAYER_SMEM_FLOATS 24768

__global__ __launch_bounds__(256, 2)
void k_layer(int ping, int layer, int dil, int last,
             const float* __restrict__ bc_g,   // conv bias (128)
             const float* __restrict__ bo_g)   // residual bias (64)
{
    const float* __restrict__ hin  = ping ? g_hB : g_hA;
    float*       __restrict__ hout = ping ? g_hA : g_hB;
    const float* __restrict__ WcT = g_WcT + layer * (3 * RCH * GCH);
    const float* __restrict__ WoT = g_WoT + layer * (RCH * RCH);
    const float* __restrict__ W1T = g_W1T + layer * (RCH * RCH);

    extern __shared__ float sm[];
    float* Hs  = sm;            // also Zs after phase1
    float* Ws  = sm + 8192;
    float* WoS = sm + 16384;
    float* W1S = sm + 20480;
    float* bcS = sm + 24576;
    float* boS = sm + 24704;

    const int tid = threadIdx.x;
    const int b   = blockIdx.y;
    const int t0  = blockIdx.x * 128;
    const int q   = tid >> 4;          // 0..15 : channel-group
    const int tj  = (tid & 15) * 8;    // 0..120: time-subtile

    // persistent small weights
    for (int u = tid; u < RCH * RCH; u += 256) { WoS[u] = WoT[u]; W1S[u] = W1T[u]; }
    if (tid < GCH) bcS[tid] = bc_g[tid];
    if (tid < RCH) boS[tid] = bo_g[tid];

    const float* hin_b = hin + (size_t)b * RCH * TLEN;

    // ---- phase 1: conv GEMM, rows split {r, r+64} so gating stays in-thread ----
    float accL[4][8], accH[4][8];
#pragma unroll
    for (int i = 0; i < 4; i++)
#pragma unroll
        for (int j = 0; j < 8; j++) { accL[i][j] = 0.f; accH[i][j] = 0.f; }

    for (int k = 0; k < 3; k++) {
        __syncthreads();
        const int off = t0 - (2 - k) * dil;
        for (int u = tid; u < RCH * 128; u += 256) {
            int ci = u >> 7, j = u & 127;
            int col = off + j;
            Hs[u] = (col >= 0) ? hin_b[(size_t)ci * TLEN + col] : 0.0f;
        }
        const float* Wk = WcT + k * (RCH * GCH);
        for (int u = tid; u < RCH * GCH; u += 256) Ws[u] = Wk[u];
        __syncthreads();

#pragma unroll 4
        for (int ci = 0; ci < RCH; ci++) {
            const float4 wl = *reinterpret_cast<const float4*>(&Ws[ci * GCH + (q << 2)]);
            const float4 wh = *reinterpret_cast<const float4*>(&Ws[ci * GCH + RCH + (q << 2)]);
            const float4 h0 = *reinterpret_cast<const float4*>(&Hs[ci * 128 + tj]);
            const float4 h1 = *reinterpret_cast<const float4*>(&Hs[ci * 128 + tj + 4]);
            const float hv[8]  = {h0.x, h0.y, h0.z, h0.w, h1.x, h1.y, h1.z, h1.w};
            const float wlv[4] = {wl.x, wl.y, wl.z, wl.w};
            const float whv[4] = {wh.x, wh.y, wh.z, wh.w};
#pragma unroll
            for (int i = 0; i < 4; i++)
#pragma unroll
                for (int j = 0; j < 8; j++) {
                    accL[i][j] += wlv[i] * hv[j];
                    accH[i][j] += whv[i] * hv[j];
                }
        }
    }
    __syncthreads();   // done reading Hs/Ws; safe to overlay Zs

    // ---- phase 2: gated activation, in-register -> Zs ----
#pragma unroll
    for (int i = 0; i < 4; i++) {
        const float ba = bcS[(q << 2) + i];
        const float bg = bcS[RCH + (q << 2) + i];
#pragma unroll
        for (int j = 0; j < 8; j++) {
            float a = accL[i][j] + ba;
            float g = accH[i][j] + bg;
            float z = tanhf(a) * (1.0f / (1.0f + __expf(-g)));
            Hs[((q << 2) + i) * 128 + tj + j] = z;   // Zs overlay
        }
    }
    __syncthreads();

    // ---- phase 3: residual (Wo) and skip-projection (W1) 64x64 GEMMs ----
    float acc2[4][8], acc3[4][8];
#pragma unroll
    for (int i = 0; i < 4; i++)
#pragma unroll
        for (int j = 0; j < 8; j++) { acc2[i][j] = 0.f; acc3[i][j] = 0.f; }

    const int r0 = q << 2;
#pragma unroll 4
    for (int rl = 0; rl < RCH; rl++) {
        const float4 z0 = *reinterpret_cast<const float4*>(&Hs[rl * 128 + tj]);
        const float4 z1 = *reinterpret_cast<const float4*>(&Hs[rl * 128 + tj + 4]);
        const float zv[8] = {z0.x, z0.y, z0.z, z0.w, z1.x, z1.y, z1.z, z1.w};
        const float4 w1v = *reinterpret_cast<const float4*>(&W1S[rl * RCH + r0]);
        const float w1a[4] = {w1v.x, w1v.y, w1v.z, w1v.w};
#pragma unroll
        for (int i = 0; i < 4; i++)
#pragma unroll
            for (int j = 0; j < 8; j++) acc3[i][j] += w1a[i] * zv[j];
        if (!last) {
            const float4 wov = *reinterpret_cast<const float4*>(&WoS[rl * RCH + r0]);
            const float woa[4] = {wov.x, wov.y, wov.z, wov.w};
#pragma unroll
            for (int i = 0; i < 4; i++)
#pragma unroll
                for (int j = 0; j < 8; j++) acc2[i][j] += woa[i] * zv[j];
        }
    }

    // ---- epilogue: skip RMW, residual write ----
#pragma unroll
    for (int i = 0; i < 4; i++) {
        const int r = r0 + i;
        const size_t base = (size_t)(b * RCH + r) * TLEN + t0 + tj;
        float4 s0 = *reinterpret_cast<const float4*>(&g_skip[base]);
        float4 s1 = *reinterpret_cast<const float4*>(&g_skip[base + 4]);
        s0.x += acc3[i][0]; s0.y += acc3[i][1]; s0.z += acc3[i][2]; s0.w += acc3[i][3];
        s1.x += acc3[i][4]; s1.y += acc3[i][5]; s1.z += acc3[i][6]; s1.w += acc3[i][7];
        *reinterpret_cast<float4*>(&g_skip[base])     = s0;
        *reinterpret_cast<float4*>(&g_skip[base + 4]) = s1;
        if (!last) {
            const float bo = boS[r];
            float4 h0 = *reinterpret_cast<const float4*>(&hin_b[(size_t)r * TLEN + t0 + tj]);
            float4 h1 = *reinterpret_cast<const float4*>(&hin_b[(size_t)r * TLEN + t0 + tj + 4]);
            h0.x += bo + acc2[i][0]; h0.y += bo + acc2[i][1];
            h0.z += bo + acc2[i][2]; h0.w += bo + acc2[i][3];
            h1.x += bo + acc2[i][4]; h1.y += bo + acc2[i][5];
            h1.z += bo + acc2[i][6]; h1.w += bo + acc2[i][7];
            float* hout_b = hout + (size_t)b * RCH * TLEN;
            *reinterpret_cast<float4*>(&hout_b[(size_t)r * TLEN + t0 + tj])     = h0;
            *reinterpret_cast<float4*>(&hout_b[(size_t)r * TLEN + t0 + tj + 4]) = h1;
        }
    }
}

// ---------------- output head: out = W2 * tanh(skip + b1) + b2 ----------------
// smem: Ss [r][t] 64x128 (8192) | W2s [r][co] 64x256 (16384) | b2s (256) | b1s (64)
#define OUT_SMEM_FLOATS 24896

__global__ __launch_bounds__(512, 1)
void k_out(const float* __restrict__ b1_g, const float* __restrict__ b2_g,
           float* __restrict__ out)
{
    extern __shared__ float sm[];
    float* Ss  = sm;
    float* W2s = sm + 8192;
    float* b2s = sm + 24576;
    float* b1s = sm + 24832;

    const int tid = threadIdx.x;
    const int b   = blockIdx.y;
    const int t0  = blockIdx.x * 128;

    if (tid < RCH)   b1s[tid] = b1_g[tid];
    if (tid < NCOUT) b2s[tid] = b2_g[tid];
    for (int u = tid; u < RCH * NCOUT; u += 512) W2s[u] = g_W2T[u];
    __syncthreads();
    for (int u = tid; u < RCH * 128; u += 512) {
        int r = u >> 7, j = u & 127;
        Ss[u] = tanhf(g_skip[(size_t)(b * RCH + r) * TLEN + t0 + j] + b1s[r]);
    }
    __syncthreads();

    const int co0 = (tid >> 4) * 8;     // 32 groups x 8 = 256
    const int tj  = (tid & 15) * 8;
    float acc[8][8];
#pragma unroll
    for (int i = 0; i < 8; i++)
#pragma unroll
        for (int j = 0; j < 8; j++) acc[i][j] = 0.f;

#pragma unroll 4
    for (int r = 0; r < RCH; r++) {
        const float4 wa = *reinterpret_cast<const float4*>(&W2s[r * NCOUT + co0]);
        const float4 wb = *reinterpret_cast<const float4*>(&W2s[r * NCOUT + co0 + 4]);
        const float4 z0 = *reinterpret_cast<const float4*>(&Ss[r * 128 + tj]);
        const float4 z1 = *reinterpret_cast<const float4*>(&Ss[r * 128 + tj + 4]);
        const float wv[8] = {wa.x, wa.y, wa.z, wa.w, wb.x, wb.y, wb.z, wb.w};
        const float zv[8] = {z0.x, z0.y, z0.z, z0.w, z1.x, z1.y, z1.z, z1.w};
#pragma unroll
        for (int i = 0; i < 8; i++)
#pragma unroll
            for (int j = 0; j < 8; j++) acc[i][j] += wv[i] * zv[j];
    }

#pragma unroll
    for (int i = 0; i < 8; i++) {
        const int co = co0 + i;
        const float bias = b2s[co];
        const size_t base = (size_t)(b * NCOUT + co) * TLEN + t0 + tj;
        float4 o0, o1;
        o0.x = acc[i][0] + bias; o0.y = acc[i][1] + bias;
        o0.z = acc[i][2] + bias; o0.w = acc[i][3] + bias;
        o1.x = acc[i][4] + bias; o1.y = acc[i][5] + bias;
        o1.z = acc[i][6] + bias; o1.w = acc[i][7] + bias;
        *reinterpret_cast<float4*>(&out[base])     = o0;
        *reinterpret_cast<float4*>(&out[base + 4]) = o1;
    }
}

// ---------------- launch ----------------
extern "C" void kernel_launch(void* const* d_in, const int* in_sizes, int n_in,
                              void* d_out, int out_size)
{
    (void)in_sizes; (void)n_in; (void)out_size;
    const float* x   = (const float*)d_in[0];   // (4,1,32768)
    const float* wi  = (const float*)d_in[1];   // (64,1,1)
    const float* bi  = (const float*)d_in[2];   // (64,)
    const float* wc  = (const float*)d_in[3];   // (9,128,64,3)
    const float* bc  = (const float*)d_in[4];   // (9,128)
    const float* wo  = (const float*)d_in[5];   // (9,64,64,1)
    const float* bo  = (const float*)d_in[6];   // (9,64)
    const float* w1  = (const float*)d_in[7];   // (64,576,1)
    const float* b1  = (const float*)d_in[8];   // (64,)
    const float* w2  = (const float*)d_in[9];   // (256,64,1)
    const float* b2  = (const float*)d_in[10];  // (256,)
    float* out = (float*)d_out;

    static const int dils[NLAY] = {1, 2, 4, 8, 16, 32, 64, 128, 256};

    const int layer_smem = LAYER_SMEM_FLOATS * (int)sizeof(float);  // ~99 KB
    const int out_smem   = OUT_SMEM_FLOATS   * (int)sizeof(float);  // ~100 KB
    cudaFuncSetAttribute(k_layer, cudaFuncAttributeMaxDynamicSharedMemorySize, layer_smem);
    cudaFuncSetAttribute(k_out,   cudaFuncAttributeMaxDynamicSharedMemorySize, out_smem);

    dim3 tiles(TLEN / 128, BATCH);   // 256 x 4

    k_prep<<<256, 256>>>(wc, wo, w1, w2);
    k_init<<<tiles, 256>>>(x, wi, bi);

    int ping = 0;  // 0: hin = g_hA
    for (int l = 0; l < NLAY; l++) {
        const int last = (l == NLAY - 1) ? 1 : 0;
        k_layer<<<tiles, 256, layer_smem>>>(ping, l, dils[l], last,
                                            bc + l * GCH, bo + l * RCH);
        ping ^= 1;
    }

    k_out<<<tiles, 512, out_smem>>>(b1, b2, out);
}

// round 6
// speedup vs baseline: 1.0968x; 1.0968x over previous
#include <cuda_runtime.h>
#include <cstdint>

// ---------------- problem constants (fixed shapes) ----------------
#define TLEN   32768
#define BATCH  4
#define RCH    64          // residual channels
#define GCH    128         // 2R gate channels
#define NLAY   9
#define NCOUT  256

typedef unsigned long long ull;

// ---- packed f32x2 helpers (SASS FFMA2 path) ----
__device__ __forceinline__ void fma2(ull& acc, ull a, ull b) {
    asm("fma.rn.f32x2 %0, %1, %2, %0;" : "+l"(acc) : "l"(a), "l"(b));
}
__device__ __forceinline__ ull dup2(float x) {
    ull r; asm("mov.b64 %0, {%1, %1};" : "=l"(r) : "f"(x)); return r;
}
__device__ __forceinline__ void unpack2(ull v, float& lo, float& hi) {
    asm("mov.b64 {%0, %1}, %2;" : "=f"(lo), "=f"(hi) : "l"(v));
}

// ---------------- device scratch ----------------
__device__ float g_hA  [BATCH * RCH * TLEN];     // 33.5 MB
__device__ float g_hB  [BATCH * RCH * TLEN];     // 33.5 MB
__device__ float g_skip[BATCH * RCH * TLEN];     // 33.5 MB
__device__ float g_WcT [NLAY * 3 * RCH * GCH];   // [l][k][ci][r*2 + {lo:co=r, hi:co=r+64}]
__device__ float g_WoW1[NLAY * RCH * GCH];       // [l][rl][r*2 + {lo:Wo, hi:W1}]
__device__ float g_W2T [RCH * NCOUT];            // [r][co]  (adjacent co = natural pairs)

// ---------------- weight repack (runs once per launch) ----------------
__global__ void k_prep(const float* __restrict__ wc,   // (L,128,64,3)
                       const float* __restrict__ wo,   // (L,64,64,1)
                       const float* __restrict__ w1,   // (64, 64*L, 1)
                       const float* __restrict__ w2)   // (256,64,1)
{
    const int N_WC = NLAY * 3 * RCH * GCH;   // 221184
    const int N_OW = NLAY * RCH * GCH;       // 73728
    const int N_W2 = RCH * NCOUT;            // 16384
    const int total = N_WC + N_OW + N_W2;
    for (int u = blockIdx.x * blockDim.x + threadIdx.x; u < total;
         u += gridDim.x * blockDim.x) {
        int v = u;
        if (v < N_WC) {
            int l  = v / 24576;
            int r0 = v % 24576;
            int k  = r0 / 8192;
            int r1 = r0 % 8192;
            int ci = r1 / GCH;
            int u2 = r1 % GCH;
            int r  = u2 >> 1;
            int p  = u2 & 1;
            int co = r + p * RCH;
            g_WcT[v] = wc[((l * GCH + co) * RCH + ci) * 3 + k];
            continue;
        }
        v -= N_WC;
        if (v < N_OW) {
            int l  = v / 8192;
            int r1 = v % 8192;
            int rl = r1 / GCH;
            int u2 = r1 % GCH;
            int r  = u2 >> 1;
            int p  = u2 & 1;
            g_WoW1[v] = p ? w1[r * (RCH * NLAY) + l * RCH + rl]
                          : wo[(l * RCH + r) * RCH + rl];
            continue;
        }
        v -= N_OW;
        {
            int r  = v / NCOUT;
            int co = v % NCOUT;
            g_W2T[v] = w2[co * RCH + r];
        }
    }
}

// ---------------- input 1x1 conv + tanh, and zero skip accumulator ----------------
__global__ __launch_bounds__(256) void k_init(const float* __restrict__ x,
                                              const float* __restrict__ wi,
                                              const float* __restrict__ bi)
{
    __shared__ float xs[128];
    __shared__ float wis[RCH];
    __shared__ float bis[RCH];
    const int b  = blockIdx.y;
    const int t0 = blockIdx.x * 128;
    const int tid = threadIdx.x;
    if (tid < 128)          xs[tid]        = x[b * TLEN + t0 + tid];
    else if (tid < 192)     wis[tid - 128] = wi[tid - 128];
    else                    bis[tid - 192] = bi[tid - 192];
    __syncthreads();
    for (int u = tid; u < RCH * 128; u += 256) {
        int r = u >> 7, j = u & 127;
        size_t idx = (size_t)(b * RCH + r) * TLEN + t0 + j;
        g_hA[idx]   = tanhf(wis[r] * xs[j] + bis[r]);
        g_skip[idx] = 0.0f;
    }
}

// ---------------- fused layer: dilated conv + gate + residual + skip-proj ----------------
// smem (floats):
//   [0     .. 8192)   Hs : input tile [ci][t] 64x128 (phase1); Zs overlay (phase2/3)
//   [8192  .. 16384)  Ws : tap weights, (wl,wh)-interleaved [ci][r*2+p] 64x128
//   [16384 .. 24576)  OW : (wo,w1)-interleaved [rl][r*2+p] 64x128
//   [24576 .. 24704)  bcS (128)
//   [24704 .. 24768)  boS (64)
#define LAYER_SMEM_FLOATS 24768

__global__ __launch_bounds__(256, 2)
void k_layer(int ping, int layer, int dil, int last,
             const float* __restrict__ bc_g,
             const float* __restrict__ bo_g)
{
    const float* __restrict__ hin  = ping ? g_hB : g_hA;
    float*       __restrict__ hout = ping ? g_hA : g_hB;
    const float* __restrict__ WcT = g_WcT  + layer * (3 * RCH * GCH);
    const float* __restrict__ OWT = g_WoW1 + layer * (RCH * GCH);

    extern __shared__ float sm[];
    float* Hs  = sm;            // also Zs after phase1
    float* Ws  = sm + 8192;
    float* OWs = sm + 16384;
    float* bcS = sm + 24576;
    float* boS = sm + 24704;

    const int tid = threadIdx.x;
    const int b   = blockIdx.y;
    const int t0  = blockIdx.x * 128;
    const int q   = tid >> 4;          // 0..15 : channel-pair group (rows r0..r0+3)
    const int tj  = (tid & 15) * 8;    // 0..120: time-subtile
    const int r0  = q << 2;

    for (int u = tid; u < RCH * GCH; u += 256) OWs[u] = OWT[u];
    if (tid < GCH) bcS[tid] = bc_g[tid];
    if (tid < RCH) boS[tid] = bo_g[tid];

    const float* hin_b = hin + (size_t)b * RCH * TLEN;

    // ---- phase 1: conv GEMM; acc pair = (gate_a, gate_g) for row r ----
    ull acc[4][8];
#pragma unroll
    for (int i = 0; i < 4; i++)
#pragma unroll
        for (int j = 0; j < 8; j++) acc[i][j] = 0ull;

    for (int k = 0; k < 3; k++) {
        __syncthreads();
        const int off = t0 - (2 - k) * dil;
        for (int u = tid; u < RCH * 128; u += 256) {
            int ci = u >> 7, j = u & 127;
            int col = off + j;
            Hs[u] = (col >= 0) ? hin_b[(size_t)ci * TLEN + col] : 0.0f;
        }
        const float* Wk = WcT + k * (RCH * GCH);
        for (int u = tid; u < RCH * GCH; u += 256) Ws[u] = Wk[u];
        __syncthreads();

#pragma unroll 4
        for (int ci = 0; ci < RCH; ci++) {
            const ulonglong2 wA = *reinterpret_cast<const ulonglong2*>(&Ws[ci * GCH + (r0 << 1)]);
            const ulonglong2 wB = *reinterpret_cast<const ulonglong2*>(&Ws[ci * GCH + (r0 << 1) + 4]);
            const float4 h0 = *reinterpret_cast<const float4*>(&Hs[ci * 128 + tj]);
            const float4 h1 = *reinterpret_cast<const float4*>(&Hs[ci * 128 + tj + 4]);
            const ull wv[4] = {wA.x, wA.y, wB.x, wB.y};
            const ull hd[8] = {dup2(h0.x), dup2(h0.y), dup2(h0.z), dup2(h0.w),
                               dup2(h1.x), dup2(h1.y), dup2(h1.z), dup2(h1.w)};
#pragma unroll
            for (int i = 0; i < 4; i++)
#pragma unroll
                for (int j = 0; j < 8; j++) fma2(acc[i][j], wv[i], hd[j]);
        }
    }
    __syncthreads();   // done with Hs/Ws; safe to overlay Zs

    // ---- phase 2: gated activation -> Zs ----
#pragma unroll
    for (int i = 0; i < 4; i++) {
        const float ba = bcS[r0 + i];
        const float bg = bcS[RCH + r0 + i];
#pragma unroll
        for (int j = 0; j < 8; j++) {
            float a, g;
            unpack2(acc[i][j], a, g);
            a += ba; g += bg;
            float z = tanhf(a) * (1.0f / (1.0f + __expf(-g)));
            Hs[(r0 + i) * 128 + tj + j] = z;
        }
    }
    __syncthreads();

    // ---- phase 3: residual + skip GEMMs; acc pair = (Wo-res, W1-skip), shared z ----
    ull acc23[4][8];
#pragma unroll
    for (int i = 0; i < 4; i++)
#pragma unroll
        for (int j = 0; j < 8; j++) acc23[i][j] = 0ull;

#pragma unroll 4
    for (int rl = 0; rl < RCH; rl++) {
        const ulonglong2 wA = *reinterpret_cast<const ulonglong2*>(&OWs[rl * GCH + (r0 << 1)]);
        const ulonglong2 wB = *reinterpret_cast<const ulonglong2*>(&OWs[rl * GCH + (r0 << 1) + 4]);
        const float4 z0 = *reinterpret_cast<const float4*>(&Hs[rl * 128 + tj]);
        const float4 z1 = *reinterpret_cast<const float4*>(&Hs[rl * 128 + tj + 4]);
        const ull wv[4] = {wA.x, wA.y, wB.x, wB.y};
        const ull zd[8] = {dup2(z0.x), dup2(z0.y), dup2(z0.z), dup2(z0.w),
                           dup2(z1.x), dup2(z1.y), dup2(z1.z), dup2(z1.w)};
#pragma unroll
        for (int i = 0; i < 4; i++)
#pragma unroll
            for (int j = 0; j < 8; j++) fma2(acc23[i][j], wv[i], zd[j]);
    }

    // ---- epilogue: skip RMW, residual write ----
#pragma unroll
    for (int i = 0; i < 4; i++) {
        const int r = r0 + i;
        const size_t base = (size_t)(b * RCH + r) * TLEN + t0 + tj;
        float res[8], skp[8];
#pragma unroll
        for (int j = 0; j < 8; j++) unpack2(acc23[i][j], res[j], skp[j]);

        float4 s0 = *reinterpret_cast<const float4*>(&g_skip[base]);
        float4 s1 = *reinterpret_cast<const float4*>(&g_skip[base + 4]);
        s0.x += skp[0]; s0.y += skp[1]; s0.z += skp[2]; s0.w += skp[3];
        s1.x += skp[4]; s1.y += skp[5]; s1.z += skp[6]; s1.w += skp[7];
        *reinterpret_cast<float4*>(&g_skip[base])     = s0;
        *reinterpret_cast<float4*>(&g_skip[base + 4]) = s1;

        if (!last) {
            const float bo = boS[r];
            float4 h0 = *reinterpret_cast<const float4*>(&hin_b[(size_t)r * TLEN + t0 + tj]);
            float4 h1 = *reinterpret_cast<const float4*>(&hin_b[(size_t)r * TLEN + t0 + tj + 4]);
            h0.x += bo + res[0]; h0.y += bo + res[1];
            h0.z += bo + res[2]; h0.w += bo + res[3];
            h1.x += bo + res[4]; h1.y += bo + res[5];
            h1.z += bo + res[6]; h1.w += bo + res[7];
            float* hout_b = hout + (size_t)b * RCH * TLEN;
            *reinterpret_cast<float4*>(&hout_b[(size_t)r * TLEN + t0 + tj])     = h0;
            *reinterpret_cast<float4*>(&hout_b[(size_t)r * TLEN + t0 + tj + 4]) = h1;
        }
    }
}

// ---------------- output head: out = W2 * tanh(skip + b1) + b2 ----------------
// smem: Ss 64x128 (8192) | W2s 64x256 (16384) | b2s (256) | b1s (64)
#define OUT_SMEM_FLOATS 24896

__global__ __launch_bounds__(512, 1)
void k_out(const float* __restrict__ b1_g, const float* __restrict__ b2_g,
           float* __restrict__ out)
{
    extern __shared__ float sm[];
    float* Ss  = sm;
    float* W2s = sm + 8192;
    float* b2s = sm + 24576;
    float* b1s = sm + 24832;

    const int tid = threadIdx.x;
    const int b   = blockIdx.y;
    const int t0  = blockIdx.x * 128;

    if (tid < RCH)   b1s[tid] = b1_g[tid];
    if (tid < NCOUT) b2s[tid] = b2_g[tid];
    for (int u = tid; u < RCH * NCOUT; u += 512) W2s[u] = g_W2T[u];
    __syncthreads();
    for (int u = tid; u < RCH * 128; u += 512) {
        int r = u >> 7, j = u & 127;
        Ss[u] = tanhf(g_skip[(size_t)(b * RCH + r) * TLEN + t0 + j] + b1s[r]);
    }
    __syncthreads();

    const int co0 = (tid >> 4) * 8;     // 32 groups x 8 co = 256
    const int tj  = (tid & 15) * 8;
    // acc pair p covers co = co0+2p, co0+2p+1
    ull acc[4][8];
#pragma unroll
    for (int p = 0; p < 4; p++)
#pragma unroll
        for (int j = 0; j < 8; j++) acc[p][j] = 0ull;

#pragma unroll 4
    for (int r = 0; r < RCH; r++) {
        const ulonglong2 wA = *reinterpret_cast<const ulonglong2*>(&W2s[r * NCOUT + co0]);
        const ulonglong2 wB = *reinterpret_cast<const ulonglong2*>(&W2s[r * NCOUT + co0 + 4]);
        const float4 z0 = *reinterpret_cast<const float4*>(&Ss[r * 128 + tj]);
        const float4 z1 = *reinterpret_cast<const float4*>(&Ss[r * 128 + tj + 4]);
        const ull wv[4] = {wA.x, wA.y, wB.x, wB.y};
        const ull zd[8] = {dup2(z0.x), dup2(z0.y), dup2(z0.z), dup2(z0.w),
                           dup2(z1.x), dup2(z1.y), dup2(z1.z), dup2(z1.w)};
#pragma unroll
        for (int p = 0; p < 4; p++)
#pragma unroll
            for (int j = 0; j < 8; j++) fma2(acc[p][j], wv[p], zd[j]);
    }

#pragma unroll
    for (int p = 0; p < 4; p++) {
        float lo[8], hi[8];
#pragma unroll
        for (int j = 0; j < 8; j++) unpack2(acc[p][j], lo[j], hi[j]);
        const int coA = co0 + 2 * p;
        const int coB = coA + 1;
        const float bA = b2s[coA], bB = b2s[coB];
        const size_t baseA = (size_t)(b * NCOUT + coA) * TLEN + t0 + tj;
        const size_t baseB = (size_t)(b * NCOUT + coB) * TLEN + t0 + tj;
        float4 oa0 = {lo[0] + bA, lo[1] + bA, lo[2] + bA, lo[3] + bA};
        float4 oa1 = {lo[4] + bA, lo[5] + bA, lo[6] + bA, lo[7] + bA};
        float4 ob0 = {hi[0] + bB, hi[1] + bB, hi[2] + bB, hi[3] + bB};
        float4 ob1 = {hi[4] + bB, hi[5] + bB, hi[6] + bB, hi[7] + bB};
        *reinterpret_cast<float4*>(&out[baseA])     = oa0;
        *reinterpret_cast<float4*>(&out[baseA + 4]) = oa1;
        *reinterpret_cast<float4*>(&out[baseB])     = ob0;
        *reinterpret_cast<float4*>(&out[baseB + 4]) = ob1;
    }
}

// ---------------- launch ----------------
extern "C" void kernel_launch(void* const* d_in, const int* in_sizes, int n_in,
                              void* d_out, int out_size)
{
    (void)in_sizes; (void)n_in; (void)out_size;
    const float* x   = (const float*)d_in[0];   // (4,1,32768)
    const float* wi  = (const float*)d_in[1];   // (64,1,1)
    const float* bi  = (const float*)d_in[2];   // (64,)
    const float* wc  = (const float*)d_in[3];   // (9,128,64,3)
    const float* bc  = (const float*)d_in[4];   // (9,128)
    const float* wo  = (const float*)d_in[5];   // (9,64,64,1)
    const float* bo  = (const float*)d_in[6];   // (9,64)
    const float* w1  = (const float*)d_in[7];   // (64,576,1)
    const float* b1  = (const float*)d_in[8];   // (64,)
    const float* w2  = (const float*)d_in[9];   // (256,64,1)
    const float* b2  = (const float*)d_in[10];  // (256,)
    float* out = (float*)d_out;

    static const int dils[NLAY] = {1, 2, 4, 8, 16, 32, 64, 128, 256};

    const int layer_smem = LAYER_SMEM_FLOATS * (int)sizeof(float);
    const int out_smem   = OUT_SMEM_FLOATS   * (int)sizeof(float);
    cudaFuncSetAttribute(k_layer, cudaFuncAttributeMaxDynamicSharedMemorySize, layer_smem);
    cudaFuncSetAttribute(k_out,   cudaFuncAttributeMaxDynamicSharedMemorySize, out_smem);

    dim3 tiles(TLEN / 128, BATCH);   // 256 x 4

    k_prep<<<256, 256>>>(wc, wo, w1, w2);
    k_init<<<tiles, 256>>>(x, wi, bi);

    int ping = 0;
    for (int l = 0; l < NLAY; l++) {
        const int last = (l == NLAY - 1) ? 1 : 0;
        k_layer<<<tiles, 256, layer_smem>>>(ping, l, dils[l], last,
                                            bc + l * GCH, bo + l * RCH);
        ping ^= 1;
    }

    k_out<<<tiles, 512, out_smem>>>(b1, b2, out);
}